// round 9
// baseline (speedup 1.0000x reference)
#include <cuda_runtime.h>
#include <math.h>

// Problem shape (fixed by dataset): N=100000, H=32, K=15, C_in=C_out=64
#define MAXN 100000
#define NB_H 32
#define KPTS 15
#define CH   64

#define NBLOCKS       592                // 148 SMs x 4 (co-resident via __launch_bounds__(256,4))
#define NTHREADS      256
#define TOTAL_THREADS (NBLOCKS * NTHREADS)
#define TOTAL_WARPS   (NBLOCKS * 8)

// Scratch (__device__ globals: allocation-free rule)
__device__ float4 g_pts4[MAXN];      // s_pts packed as float4 (w unused)
__device__ float  g_val[MAXN * CH];  // raw kpconv rows for flagged points
__device__ int    g_flag[MAXN];      // 1 if row active
__device__ float  g_sum[CH];
__device__ float  g_sumsq[CH];
// software grid barrier (self-resetting, safe across graph replays)
__device__ int          g_bar_count = 0;
__device__ volatile int g_bar_gen   = 0;

static __host__ __device__ __forceinline__ float kp_extent() {
    return (float)(0.1 * 1.2 / 2.5);
}

static __device__ __forceinline__ void grid_sync() {
    __threadfence();
    __syncthreads();
    if (threadIdx.x == 0) {
        const int gen = g_bar_gen;
        if (atomicAdd(&g_bar_count, 1) == NBLOCKS - 1) {
            g_bar_count = 0;
            __threadfence();
            g_bar_gen = gen + 1;
        } else {
            while (g_bar_gen == gen) { __nanosleep(32); }
        }
    }
    __syncthreads();
}

// Warp-cooperative exact KPConv for one point n (rare path, ~100 executions total).
static __device__ void heavy_point(
    int n, int lane, float thr2,
    const float* __restrict__ q_pts, const int* __restrict__ inds,
    const float* __restrict__ x, const float* __restrict__ kp,
    const float* __restrict__ W, int N, float sw_k[KPTS][CH])
{
    const unsigned FULL = 0xffffffffu;
    const float EXT  = kp_extent();
    const float EXT2 = EXT * EXT;
    const float INVE = 1.0f / EXT;

    const float qx = __ldg(q_pts + 3*n);
    const float qy = __ldg(q_pts + 3*n + 1);
    const float qz = __ldg(q_pts + 3*n + 2);

    const int idx = __ldg(inds + (long)n * NB_H + lane);
    const bool valid = ((unsigned)idx < (unsigned)N);
    float nx = 1e9f, ny = 1e9f, nz = 1e9f;
    if (valid) {
        const float4 p = __ldg(&g_pts4[idx]);
        nx = p.x - qx; ny = p.y - qy; nz = p.z - qz;
    }
    const float r2 = fmaf(nx, nx, fmaf(ny, ny, nz * nz));
    unsigned mask = __ballot_sync(FULL, valid && (r2 < thr2));

    float acc0[KPTS], acc1[KPTS];
#pragma unroll
    for (int k = 0; k < KPTS; k++) { acc0[k] = 0.0f; acc1[k] = 0.0f; }

    unsigned m = mask;
    while (m) {
        const int hs = __ffs(m) - 1;
        m &= (m - 1);
        const int   sidx = __shfl_sync(FULL, idx, hs);
        const float bx = __shfl_sync(FULL, nx, hs);
        const float by = __shfl_sync(FULL, ny, hs);
        const float bz = __shfl_sync(FULL, nz, hs);
        const float xv0 = __ldg(x + (long)sidx * CH + lane);
        const float xv1 = __ldg(x + (long)sidx * CH + lane + 32);
#pragma unroll
        for (int k = 0; k < KPTS; k++) {
            const float dx = bx - __ldg(kp + 3*k);
            const float dy = by - __ldg(kp + 3*k + 1);
            const float dz = bz - __ldg(kp + 3*k + 2);
            const float d2 = fmaf(dx, dx, fmaf(dy, dy, dz * dz));
            if (d2 < EXT2) {
                const float w = fmaxf(1.0f - sqrtf(d2) * INVE, 0.0f);
                acc0[k] = fmaf(w, xv0, acc0[k]);
                acc1[k] = fmaf(w, xv1, acc1[k]);
            }
        }
    }

    unsigned kmask = 0;
#pragma unroll
    for (int k = 0; k < KPTS; k++) {
        sw_k[k][lane]      = acc0[k];
        sw_k[k][lane + 32] = acc1[k];
        if (__ballot_sync(FULL, (acc0[k] != 0.0f) || (acc1[k] != 0.0f)))
            kmask |= (1u << k);
    }
    __syncwarp();

    float o0 = 0.0f, o1 = 0.0f;
    for (int k = 0; k < KPTS; k++) {
        if (!(kmask & (1u << k))) continue;
        const float* Wk = W + (long)k * CH * CH;
#pragma unroll 8
        for (int c = 0; c < CH; c++) {
            const float wv = sw_k[k][c];
            o0 = fmaf(wv, __ldg(Wk + c * CH + lane),      o0);
            o1 = fmaf(wv, __ldg(Wk + c * CH + lane + 32), o1);
        }
    }
    __syncwarp();

    g_val[(long)n * CH + lane]      = o0;
    g_val[(long)n * CH + lane + 32] = o1;
    if (lane == 0) g_flag[n] = 1;
    atomicAdd(&g_sum[lane],        o0);
    atomicAdd(&g_sum[lane + 32],   o1);
    atomicAdd(&g_sumsq[lane],      o0 * o0);
    atomicAdd(&g_sumsq[lane + 32], o1 * o1);
}

__global__ void __launch_bounds__(NTHREADS, 4) fused_kernel(
    const float* __restrict__ q_pts,
    const float* __restrict__ s_pts,
    const int*   __restrict__ inds,
    const float* __restrict__ x,
    const float* __restrict__ kp,
    const float* __restrict__ W,    // [K, C, C]
    float* __restrict__ out, int N)
{
    __shared__ float sw[8][KPTS][CH];        // 30 KB, heavy-path staging
    __shared__ float mm[CH], iv[CH], zz[CH]; // phase-C stats

    const int tid   = threadIdx.x;
    const int warp  = tid >> 5;
    const int lane  = tid & 31;
    const int gwarp = blockIdx.x * 8 + warp;
    const unsigned FULL = 0xffffffffu;

    // conservative candidate threshold^2
    float thr2;
    {
        float mx2 = 0.0f;
#pragma unroll
        for (int k = 0; k < KPTS; k++) {
            const float a = __ldg(kp + 3*k), b = __ldg(kp + 3*k + 1), c = __ldg(kp + 3*k + 2);
            mx2 = fmaxf(mx2, fmaf(a, a, fmaf(b, b, c * c)));
        }
        const float t = (kp_extent() + sqrtf(mx2)) * 1.0002f + 1e-6f;  // false positives ok
        thr2 = t * t;
    }

    // ---------------- Phase A: pack s_pts, zero flags/sums ----------------
    for (int i = blockIdx.x * NTHREADS + tid; i < N; i += TOTAL_THREADS) {
        g_flag[i] = 0;
        g_pts4[i] = make_float4(__ldg(s_pts + 3*i), __ldg(s_pts + 3*i + 1),
                                __ldg(s_pts + 3*i + 2), 0.0f);
    }
    if (blockIdx.x == 0 && tid < CH) { g_sum[tid] = 0.0f; g_sumsq[tid] = 0.0f; }
    grid_sync();

    // ------- Phase B: detect (4 threads/point, 8 gathers in flight) + inline heavy -------
    {
        const int total = N * 4;                              // 4 sub-threads per point
        const int niter = (total + TOTAL_THREADS - 1) / TOTAL_THREADS;  // uniform trip count
        int g = blockIdx.x * NTHREADS + tid;

        for (int it = 0; it < niter; it++, g += TOTAL_THREADS) {
            const bool active = (g < total);
            bool hit = false;

            if (active) {
                const int n   = g >> 2;
                const int sub = g & 3;

                const float qx = __ldg(q_pts + 3*n);
                const float qy = __ldg(q_pts + 3*n + 1);
                const float qz = __ldg(q_pts + 3*n + 2);

                // two int4 quads = 8 neighbors of point n
                const int4 a = __ldg(reinterpret_cast<const int4*>(inds) + (long)n * 8 + sub * 2);
                const int4 b = __ldg(reinterpret_cast<const int4*>(inds) + (long)n * 8 + sub * 2 + 1);

                // dataset guarantees idx in [0, N): 8 independent gathers (MLP=8)
                const float4 p0 = __ldg(&g_pts4[a.x]);
                const float4 p1 = __ldg(&g_pts4[a.y]);
                const float4 p2 = __ldg(&g_pts4[a.z]);
                const float4 p3 = __ldg(&g_pts4[a.w]);
                const float4 p4 = __ldg(&g_pts4[b.x]);
                const float4 p5 = __ldg(&g_pts4[b.y]);
                const float4 p6 = __ldg(&g_pts4[b.z]);
                const float4 p7 = __ldg(&g_pts4[b.w]);

                float dx, dy, dz;
                dx = p0.x - qx; dy = p0.y - qy; dz = p0.z - qz;
                hit |= (fmaf(dx, dx, fmaf(dy, dy, dz * dz)) < thr2);
                dx = p1.x - qx; dy = p1.y - qy; dz = p1.z - qz;
                hit |= (fmaf(dx, dx, fmaf(dy, dy, dz * dz)) < thr2);
                dx = p2.x - qx; dy = p2.y - qy; dz = p2.z - qz;
                hit |= (fmaf(dx, dx, fmaf(dy, dy, dz * dz)) < thr2);
                dx = p3.x - qx; dy = p3.y - qy; dz = p3.z - qz;
                hit |= (fmaf(dx, dx, fmaf(dy, dy, dz * dz)) < thr2);
                dx = p4.x - qx; dy = p4.y - qy; dz = p4.z - qz;
                hit |= (fmaf(dx, dx, fmaf(dy, dy, dz * dz)) < thr2);
                dx = p5.x - qx; dy = p5.y - qy; dz = p5.z - qz;
                hit |= (fmaf(dx, dx, fmaf(dy, dy, dz * dz)) < thr2);
                dx = p6.x - qx; dy = p6.y - qy; dz = p6.z - qz;
                hit |= (fmaf(dx, dx, fmaf(dy, dy, dz * dz)) < thr2);
                dx = p7.x - qx; dy = p7.y - qy; dz = p7.z - qz;
                hit |= (fmaf(dx, dx, fmaf(dy, dy, dz * dz)) < thr2);
            }

            const unsigned mask = __ballot_sync(FULL, hit);
            if (mask == 0) continue;                 // ~99.9% of iterations

            // rare: warp processes each hit point cooperatively (4 bits per point)
            const int n_warp0 = ((g - lane) >> 2);   // lane 0's point this iteration
#pragma unroll
            for (int p = 0; p < 8; p++) {
                if ((mask >> (4 * p)) & 0xFu) {
                    heavy_point(n_warp0 + p, lane, thr2,
                                q_pts, inds, x, kp, W, N, sw[warp]);
                }
            }
        }
    }
    grid_sync();

    // ---------------- Phase C: finalize stats, stream output ----------------
    if (tid < CH) {
        const float invN = 1.0f / (float)N;
        const float mean = g_sum[tid] * invN;
        const float var  = fmaxf(g_sumsq[tid] * invN - mean * mean, 0.0f);
        const float inv  = rsqrtf(var + 1e-5f);
        const float z    = (0.0f - mean) * inv;
        mm[tid] = mean;
        iv[tid] = inv;
        zz[tid] = (z >= 0.0f) ? z : 0.1f * z;
    }
    __syncthreads();

    {
        float4* __restrict__ out4 = reinterpret_cast<float4*>(out);
        const int c4 = (lane & 15) * 4;
        const float4 vz = make_float4(zz[c4], zz[c4 + 1], zz[c4 + 2], zz[c4 + 3]);
        const int ngrp = (N + 31) >> 5;   // 32-row groups

        for (int g = gwarp; g < ngrp; g += TOTAL_WARPS) {
            const int r0 = g * 32;
            const int fn = r0 + lane;
            const int f  = (fn < N) ? g_flag[fn] : 0;   // one coalesced load per warp
            const unsigned hits = __ballot_sync(FULL, f != 0);

            if (hits == 0 && r0 + 32 <= N) {
                const long base = (long)g * 512;        // float4 units (32 rows * 16)
#pragma unroll
                for (int j = 0; j < 16; j++)
                    out4[base + j * 32 + lane] = vz;
            } else {
                const int rend = min(r0 + 32, N);
                for (int r = r0; r < rend; r++) {
                    const int fr = __shfl_sync(FULL, f, r - r0);
                    float a0, a1;
                    if (fr) {
                        const float v0 = g_val[(long)r * CH + lane];
                        const float v1 = g_val[(long)r * CH + lane + 32];
                        a0 = (v0 - mm[lane])      * iv[lane];
                        a1 = (v1 - mm[lane + 32]) * iv[lane + 32];
                        a0 = (a0 >= 0.0f) ? a0 : 0.1f * a0;
                        a1 = (a1 >= 0.0f) ? a1 : 0.1f * a1;
                    } else {
                        a0 = zz[lane];
                        a1 = zz[lane + 32];
                    }
                    out[(long)r * CH + lane]      = a0;
                    out[(long)r * CH + lane + 32] = a1;
                }
            }
        }
    }
}

// ---------------- launch: ONE kernel ----------------
extern "C" void kernel_launch(void* const* d_in, const int* in_sizes, int n_in,
                              void* d_out, int out_size) {
    const float* q_pts = (const float*)d_in[0];
    const float* s_pts = (const float*)d_in[1];
    const int*   inds  = (const int*)  d_in[2];
    const float* x     = (const float*)d_in[3];
    const float* kp    = (const float*)d_in[4];
    const float* W     = (const float*)d_in[5];
    float* out = (float*)d_out;

    const int N = in_sizes[0] / 3;

    fused_kernel<<<NBLOCKS, NTHREADS>>>(q_pts, s_pts, inds, x, kp, W, out, N);
}